// round 1
// baseline (speedup 1.0000x reference)
#include <cuda_runtime.h>
#include <math.h>

#define N_NODES 50000
#define N_EDGES 800000
#define D 128
#define NLAYERS 2
#define CH 384  /* 3*D interleaved channels: e | b | s */

// ---------------- device scratch (static globals: no allocation at launch) ----
static __device__ float g_feat[(size_t)N_NODES * CH];  // pre-agg features (3 channels)
static __device__ float g_acc [(size_t)N_NODES * CH];  // aggregated sums
static __device__ float g_ub  [(size_t)N_NODES * D];   // logmap0(b)
static __device__ float g_us  [(size_t)N_NODES * D];   // l2norm(s)
static __device__ float g_e   [(size_t)N_NODES * D];   // layer state
static __device__ float g_b   [(size_t)N_NODES * D];
static __device__ float g_s   [(size_t)N_NODES * D];
static __device__ int   g_indeg [N_NODES];
static __device__ int   g_outdeg[N_NODES];
static __device__ int   g_cursor[N_NODES];
static __device__ int   g_off [N_NODES + 1];
static __device__ int   g_csr [N_EDGES];
static __device__ float g_norm_out[N_NODES];
static __device__ float g_norm_in [N_NODES];
static __device__ float g_inv_in  [N_NODES];

// ---------------- small helpers ----------------------------------------------
__device__ __forceinline__ float4 f4add(float4 a, float4 b) {
    return make_float4(a.x + b.x, a.y + b.y, a.z + b.z, a.w + b.w);
}
__device__ __forceinline__ float4 f4scale(float4 a, float s) {
    return make_float4(a.x * s, a.y * s, a.z * s, a.w * s);
}
__device__ __forceinline__ float warp_sum(float v) {
#pragma unroll
    for (int o = 16; o > 0; o >>= 1) v += __shfl_xor_sync(0xffffffffu, v, o);
    return v;
}

// ---------------- graph preprocessing ----------------------------------------
__global__ void k_zero() {
    int i = blockIdx.x * blockDim.x + threadIdx.x;
    if (i < N_NODES) { g_indeg[i] = 0; g_outdeg[i] = 0; g_cursor[i] = 0; }
}

__global__ void k_deg(const int* __restrict__ src, const int* __restrict__ dst) {
    int e = blockIdx.x * blockDim.x + threadIdx.x;
    if (e < N_EDGES) {
        atomicAdd(&g_outdeg[src[e]], 1);
        atomicAdd(&g_indeg[dst[e]], 1);
    }
}

// single-block exclusive scan of g_indeg -> g_off
__global__ void k_scan() {
    __shared__ int wsum[32];
    __shared__ int carry;
    int tid = threadIdx.x;
    if (tid == 0) carry = 0;
    __syncthreads();
    for (int base = 0; base < N_NODES; base += 1024) {
        int i = base + tid;
        int v = (i < N_NODES) ? g_indeg[i] : 0;
        int x = v;
#pragma unroll
        for (int o = 1; o < 32; o <<= 1) {
            int y = __shfl_up_sync(0xffffffffu, x, o);
            if ((tid & 31) >= o) x += y;
        }
        if ((tid & 31) == 31) wsum[tid >> 5] = x;
        __syncthreads();
        if (tid < 32) {
            int w = wsum[tid];
#pragma unroll
            for (int o = 1; o < 32; o <<= 1) {
                int y = __shfl_up_sync(0xffffffffu, w, o);
                if (tid >= o) w += y;
            }
            wsum[tid] = w;
        }
        __syncthreads();
        int add = (tid >= 32) ? wsum[(tid >> 5) - 1] : 0;
        int incl = x + add;
        if (i < N_NODES) g_off[i] = carry + incl - v;  // exclusive
        int total = wsum[31];
        __syncthreads();
        if (tid == 0) carry += total;
        __syncthreads();
    }
    if (tid == 0) g_off[N_NODES] = carry;
}

__global__ void k_scatter(const int* __restrict__ src, const int* __restrict__ dst) {
    int e = blockIdx.x * blockDim.x + threadIdx.x;
    if (e < N_EDGES) {
        int d = dst[e];
        int p = atomicAdd(&g_cursor[d], 1);
        g_csr[g_off[d] + p] = src[e];
    }
}

__global__ void k_scales() {
    int i = blockIdx.x * blockDim.x + threadIdx.x;
    if (i < N_NODES) {
        int od = g_outdeg[i], id = g_indeg[i];
        g_norm_out[i] = od > 0 ? rsqrtf((float)od) : 0.0f;
        g_norm_in[i]  = id > 0 ? rsqrtf((float)id) : 0.0f;
        g_inv_in[i]   = id > 0 ? 1.0f / (float)id : 0.0f;
    }
}

// ---------------- per-layer kernels ------------------------------------------
// warp-per-node: e*norm_out -> feat ch0 ; logmap0(b) -> g_ub ; l2norm(s) -> g_us
__global__ void k_prep(const float* __restrict__ e, const float* __restrict__ b,
                       const float* __restrict__ s) {
    int gw   = (blockIdx.x * blockDim.x + threadIdx.x) >> 5;
    int lane = threadIdx.x & 31;
    if (gw >= N_NODES) return;
    size_t ro = (size_t)gw * D;

    // Euclidean pre-scale
    float4 ev = ((const float4*)(e + ro))[lane];
    ((float4*)(g_feat + (size_t)gw * CH))[lane] = f4scale(ev, g_norm_out[gw]);

    // Hyperbolic logmap0
    float4 bv = ((const float4*)(b + ro))[lane];
    float nb = sqrtf(warp_sum(bv.x * bv.x + bv.y * bv.y + bv.z * bv.z + bv.w * bv.w));
    float nc = fminf(fmaxf(nb, 1e-7f), 1.0f - 1e-5f);
    float fb = atanhf(nc) / fmaxf(nb, 1e-7f);
    ((float4*)(g_ub + ro))[lane] = f4scale(bv, fb);

    // Spherical l2norm
    float4 sv = ((const float4*)(s + ro))[lane];
    float ns = sqrtf(warp_sum(sv.x * sv.x + sv.y * sv.y + sv.z * sv.z + sv.w * sv.w));
    float fs = 1.0f / fmaxf(ns, 1e-12f);
    ((float4*)(g_us + ro))[lane] = f4scale(sv, fs);
}

// GEMM: C[row, 0:128] = act( scale(row) * A[row, 0:128] @ W^T + Bias )
// W row-major [out=j][in=k].  Block = 64 rows, 256 threads, smem: W^T (64KB) + A tile (32KB)
__global__ void k_gemm(const float* __restrict__ A, int lda,
                       const float* __restrict__ rowscale,
                       const float* __restrict__ W,
                       const float* __restrict__ Bias,
                       float* __restrict__ C, int ldc, int act) {
    extern __shared__ float sm[];
    float* Wt = sm;            // [k][j] 128x128
    float* As = sm + 16384;    // [r][k] 64x128
    int tid = threadIdx.x;

    for (int idx = tid; idx < 16384; idx += 256) {
        int j = idx >> 7, k = idx & 127;
        Wt[k * 128 + j] = W[idx];
    }
    int row0 = blockIdx.x * 64;
    for (int u = tid; u < 2048; u += 256) {
        int r = u >> 5, kk = u & 31;
        int gr = row0 + r;
        float4 v = make_float4(0.f, 0.f, 0.f, 0.f);
        if (gr < N_NODES) {
            v = ((const float4*)(A + (size_t)gr * lda))[kk];
            if (rowscale) v = f4scale(v, rowscale[gr]);
        }
        ((float4*)(As + r * 128))[kk] = v;
    }
    __syncthreads();

    int wp = tid >> 5, cc = tid & 31;  // warp wp owns rows wp*8..+7; lane cc owns cols cc*4..+3
    float acc[8][4];
#pragma unroll
    for (int i = 0; i < 8; i++)
#pragma unroll
        for (int j = 0; j < 4; j++) acc[i][j] = 0.f;

#pragma unroll 2
    for (int k4 = 0; k4 < 32; k4++) {
        float4 w0 = ((const float4*)(Wt + (k4 * 4 + 0) * 128))[cc];
        float4 w1 = ((const float4*)(Wt + (k4 * 4 + 1) * 128))[cc];
        float4 w2 = ((const float4*)(Wt + (k4 * 4 + 2) * 128))[cc];
        float4 w3 = ((const float4*)(Wt + (k4 * 4 + 3) * 128))[cc];
#pragma unroll
        for (int i = 0; i < 8; i++) {
            float4 av = ((const float4*)(As + (wp * 8 + i) * 128))[k4];
            acc[i][0] += av.x * w0.x + av.y * w1.x + av.z * w2.x + av.w * w3.x;
            acc[i][1] += av.x * w0.y + av.y * w1.y + av.z * w2.y + av.w * w3.y;
            acc[i][2] += av.x * w0.z + av.y * w1.z + av.z * w2.z + av.w * w3.z;
            acc[i][3] += av.x * w0.w + av.y * w1.w + av.z * w2.w + av.w * w3.w;
        }
    }
    float4 bb = ((const float4*)Bias)[cc];
#pragma unroll
    for (int i = 0; i < 8; i++) {
        int gr = row0 + wp * 8 + i;
        if (gr < N_NODES) {
            float4 o = make_float4(acc[i][0] + bb.x, acc[i][1] + bb.y,
                                   acc[i][2] + bb.z, acc[i][3] + bb.w);
            if (act) {
                o.x = o.x > 0.f ? o.x : 0.2f * o.x;
                o.y = o.y > 0.f ? o.y : 0.2f * o.y;
                o.z = o.z > 0.f ? o.z : 0.2f * o.z;
                o.w = o.w > 0.f ? o.w : 0.2f * o.w;
            }
            ((float4*)(C + (size_t)gr * ldc))[cc] = o;
        }
    }
}

// warp-per-node CSR gather-aggregation: acc[d] = sum_{e: dst=d} feat[src[e]]
__global__ void k_agg() {
    int node = (blockIdx.x * blockDim.x + threadIdx.x) >> 5;
    int lane = threadIdx.x & 31;
    if (node >= N_NODES) return;
    int e0 = g_off[node], e1 = g_off[node + 1];
    float4 a0 = make_float4(0.f, 0.f, 0.f, 0.f), a1 = a0, a2 = a0;
    int e = e0;
    for (; e + 4 <= e1; e += 4) {
        int i0 = g_csr[e], i1 = g_csr[e + 1], i2 = g_csr[e + 2], i3 = g_csr[e + 3];
        const float4* p0 = (const float4*)(g_feat + (size_t)i0 * CH);
        const float4* p1 = (const float4*)(g_feat + (size_t)i1 * CH);
        const float4* p2 = (const float4*)(g_feat + (size_t)i2 * CH);
        const float4* p3 = (const float4*)(g_feat + (size_t)i3 * CH);
        float4 v00 = p0[lane],      v10 = p1[lane],      v20 = p2[lane],      v30 = p3[lane];
        float4 v01 = p0[lane + 32], v11 = p1[lane + 32], v21 = p2[lane + 32], v31 = p3[lane + 32];
        float4 v02 = p0[lane + 64], v12 = p1[lane + 64], v22 = p2[lane + 64], v32 = p3[lane + 64];
        a0 = f4add(a0, f4add(f4add(v00, v10), f4add(v20, v30)));
        a1 = f4add(a1, f4add(f4add(v01, v11), f4add(v21, v31)));
        a2 = f4add(a2, f4add(f4add(v02, v12), f4add(v22, v32)));
    }
    for (; e < e1; e++) {
        const float4* p = (const float4*)(g_feat + (size_t)g_csr[e] * CH);
        a0 = f4add(a0, p[lane]);
        a1 = f4add(a1, p[lane + 32]);
        a2 = f4add(a2, p[lane + 64]);
    }
    float4* oa = (float4*)(g_acc + (size_t)node * CH);
    oa[lane] = a0; oa[lane + 32] = a1; oa[lane + 64] = a2;
}

// warp-per-node: b_out = expmap0(acc_b * inv_in), s_out = l2norm(acc_s * inv_in)
__global__ void k_post(float* __restrict__ bout, float* __restrict__ sout) {
    int node = (blockIdx.x * blockDim.x + threadIdx.x) >> 5;
    int lane = threadIdx.x & 31;
    if (node >= N_NODES) return;
    float ii = g_inv_in[node];
    const float* base = g_acc + (size_t)node * CH;

    float4 v = f4scale(((const float4*)(base + D))[lane], ii);
    float nb = sqrtf(warp_sum(v.x * v.x + v.y * v.y + v.z * v.z + v.w * v.w));
    float fb = tanhf(nb) / fmaxf(nb, 1e-7f);
    ((float4*)(bout + (size_t)node * D))[lane] = f4scale(v, fb);

    float4 u = f4scale(((const float4*)(base + 2 * D))[lane], ii);
    float ns = sqrtf(warp_sum(u.x * u.x + u.y * u.y + u.z * u.z + u.w * u.w));
    float fs = 1.0f / fmaxf(ns, 1e-12f);
    ((float4*)(sout + (size_t)node * D))[lane] = f4scale(u, fs);
}

// ---------------- launch ------------------------------------------------------
extern "C" void kernel_launch(void* const* d_in, const int* in_sizes, int n_in,
                              void* d_out, int out_size) {
    const float* e0  = (const float*)d_in[0];
    const float* b0  = (const float*)d_in[1];
    const float* s0  = (const float*)d_in[2];
    const float* eW  = (const float*)d_in[3];
    const float* eB  = (const float*)d_in[4];
    const float* bW  = (const float*)d_in[5];
    const float* bB  = (const float*)d_in[6];
    const float* sW  = (const float*)d_in[7];
    const float* sB  = (const float*)d_in[8];
    const int*   src = (const int*)d_in[9];
    const int*   dst = (const int*)d_in[10];
    float* out = (float*)d_out;

    cudaFuncSetAttribute(k_gemm, cudaFuncAttributeMaxDynamicSharedMemorySize, 98304);

    void* tmp;
    cudaGetSymbolAddress(&tmp, g_e);       float* pe    = (float*)tmp;
    cudaGetSymbolAddress(&tmp, g_b);       float* pb    = (float*)tmp;
    cudaGetSymbolAddress(&tmp, g_s);       float* ps    = (float*)tmp;
    cudaGetSymbolAddress(&tmp, g_ub);      float* pub   = (float*)tmp;
    cudaGetSymbolAddress(&tmp, g_us);      float* pus   = (float*)tmp;
    cudaGetSymbolAddress(&tmp, g_feat);    float* pfeat = (float*)tmp;
    cudaGetSymbolAddress(&tmp, g_acc);     float* pacc  = (float*)tmp;
    cudaGetSymbolAddress(&tmp, g_norm_in); float* pni   = (float*)tmp;

    const int node_grid = (N_NODES + 255) / 256;
    const int edge_grid = (N_EDGES + 255) / 256;
    const int warp_grid = (N_NODES + 7) / 8;       // warp-per-node, 8 warps/block
    const int gemm_grid = (N_NODES + 63) / 64;

    k_zero<<<node_grid, 256>>>();
    k_deg<<<edge_grid, 256>>>(src, dst);
    k_scan<<<1, 1024>>>();
    k_scatter<<<edge_grid, 256>>>(src, dst);
    k_scales<<<node_grid, 256>>>();

    for (int l = 0; l < NLAYERS; l++) {
        const float* ein = (l == 0) ? e0 : pe;
        const float* bin = (l == 0) ? b0 : pb;
        const float* sin = (l == 0) ? s0 : ps;
        float* eout = (l == NLAYERS - 1) ? out                          : pe;
        float* bout = (l == NLAYERS - 1) ? out + (size_t)N_NODES * D    : pb;
        float* sout = (l == NLAYERS - 1) ? out + (size_t)2 * N_NODES * D : ps;

        k_prep<<<warp_grid, 256>>>(ein, bin, sin);
        k_gemm<<<gemm_grid, 256, 98304>>>(pub, D, nullptr, bW + (size_t)l * D * D,
                                          bB + (size_t)l * D, pfeat + D, CH, 0);
        k_gemm<<<gemm_grid, 256, 98304>>>(pus, D, nullptr, sW + (size_t)l * D * D,
                                          sB + (size_t)l * D, pfeat + 2 * D, CH, 0);
        k_agg<<<warp_grid, 256>>>();
        k_gemm<<<gemm_grid, 256, 98304>>>(pacc, CH, pni, eW + (size_t)l * D * D,
                                          eB + (size_t)l * D, eout, D, 1);
        k_post<<<warp_grid, 256>>>(bout, sout);
    }
}

// round 2
// speedup vs baseline: 1.4160x; 1.4160x over previous
#include <cuda_runtime.h>
#include <math.h>

#define N_NODES 50000
#define N_EDGES 800000
#define D 128
#define NLAYERS 2
#define CH 384  /* 3*D interleaved channels: e | b | s */

// ---------------- device scratch ----------------------------------------------
static __device__ float g_feat[(size_t)N_NODES * CH];  // pre-agg features (3 channels)
static __device__ float g_acce[(size_t)N_NODES * D];   // aggregated e-channel sums
static __device__ float g_e   [(size_t)N_NODES * D];   // layer state
static __device__ float g_b   [(size_t)N_NODES * D];
static __device__ float g_s   [(size_t)N_NODES * D];
static __device__ int   g_indeg [N_NODES];
static __device__ int   g_outdeg[N_NODES];
static __device__ int   g_cursor[N_NODES];
static __device__ int   g_off [N_NODES + 1];
static __device__ int   g_part[64];
static __device__ int   g_csr [N_EDGES];
static __device__ float g_norm_out[N_NODES];
static __device__ float g_norm_in [N_NODES];
static __device__ float g_inv_in  [N_NODES];

// ---------------- helpers -------------------------------------------------------
__device__ __forceinline__ float4 f4add(float4 a, float4 b) {
    return make_float4(a.x + b.x, a.y + b.y, a.z + b.z, a.w + b.w);
}
__device__ __forceinline__ float4 f4scale(float4 a, float s) {
    return make_float4(a.x * s, a.y * s, a.z * s, a.w * s);
}
__device__ __forceinline__ float warp_sum(float v) {
#pragma unroll
    for (int o = 16; o > 0; o >>= 1) v += __shfl_xor_sync(0xffffffffu, v, o);
    return v;
}
__device__ __forceinline__ unsigned long long splat2(float x) {
    unsigned long long r;
    asm("mov.b64 %0, {%1, %1};" : "=l"(r) : "f"(x));
    return r;
}
__device__ __forceinline__ void fma2(unsigned long long& d, unsigned long long a,
                                     unsigned long long b) {
    asm("fma.rn.f32x2 %0, %1, %2, %0;" : "+l"(d) : "l"(a), "l"(b));
}
__device__ __forceinline__ float2 unpk(unsigned long long v) {
    float2 f;
    asm("mov.b64 {%0, %1}, %2;" : "=f"(f.x), "=f"(f.y) : "l"(v));
    return f;
}

// ---------------- graph preprocessing -------------------------------------------
__global__ void k_zero() {
    int i = blockIdx.x * blockDim.x + threadIdx.x;
    if (i < N_NODES) { g_indeg[i] = 0; g_outdeg[i] = 0; g_cursor[i] = 0; }
}

__global__ void k_deg(const int* __restrict__ src, const int* __restrict__ dst) {
    int e = blockIdx.x * blockDim.x + threadIdx.x;
    if (e < N_EDGES) {
        atomicAdd(&g_outdeg[src[e]], 1);
        atomicAdd(&g_indeg[dst[e]], 1);
    }
}

// phase 1: per-1024-block exclusive scan, block totals to g_part
__global__ void k_scan1() {
    __shared__ int wsum[32];
    int tid = threadIdx.x;
    int i = blockIdx.x * 1024 + tid;
    int v = (i < N_NODES) ? g_indeg[i] : 0;
    int x = v;
#pragma unroll
    for (int o = 1; o < 32; o <<= 1) {
        int y = __shfl_up_sync(0xffffffffu, x, o);
        if ((tid & 31) >= o) x += y;
    }
    if ((tid & 31) == 31) wsum[tid >> 5] = x;
    __syncthreads();
    if (tid < 32) {
        int w = wsum[tid];
#pragma unroll
        for (int o = 1; o < 32; o <<= 1) {
            int y = __shfl_up_sync(0xffffffffu, w, o);
            if (tid >= o) w += y;
        }
        wsum[tid] = w;
    }
    __syncthreads();
    int add = (tid >= 32) ? wsum[(tid >> 5) - 1] : 0;
    if (i < N_NODES) g_off[i] = x + add - v;  // block-local exclusive
    if (tid == 0) g_part[blockIdx.x] = wsum[31];
}

// phase 2: scan block totals (49 of them) — single thread is fine
__global__ void k_scan2(int nblocks) {
    if (threadIdx.x == 0) {
        int run = 0;
        for (int b = 0; b < nblocks; b++) {
            int t = g_part[b];
            g_part[b] = run;
            run += t;
        }
        g_off[N_NODES] = run;
    }
}

// phase 3: add block offsets + compute norm scales
__global__ void k_scan3() {
    int i = blockIdx.x * blockDim.x + threadIdx.x;
    if (i < N_NODES) {
        g_off[i] += g_part[i >> 10];
        int od = g_outdeg[i], id = g_indeg[i];
        g_norm_out[i] = od > 0 ? rsqrtf((float)od) : 0.0f;
        g_norm_in[i]  = id > 0 ? rsqrtf((float)id) : 0.0f;
        g_inv_in[i]   = id > 0 ? 1.0f / (float)id : 0.0f;
    }
}

__global__ void k_scatter(const int* __restrict__ src, const int* __restrict__ dst) {
    int e = blockIdx.x * blockDim.x + threadIdx.x;
    if (e < N_EDGES) {
        int d = dst[e];
        int p = atomicAdd(&g_cursor[d], 1);
        g_csr[g_off[d] + p] = src[e];
    }
}

// ---------------- e-channel pre-scale: feat ch0 = e * norm_out -------------------
__global__ void k_feat_e(const float* __restrict__ e) {
    int idx = blockIdx.x * blockDim.x + threadIdx.x;  // one float4 per thread
    if (idx >= N_NODES * (D / 4)) return;
    int node = idx >> 5;
    int c = idx & 31;
    float4 v = ((const float4*)e)[idx];
    ((float4*)(g_feat + (size_t)node * CH))[c] = f4scale(v, g_norm_out[node]);
}

// ---------------- fused GEMM body -------------------------------------------------
// C[row, 0:128] = act( pre(A[row, 0:128]) @ W^T + Bias )
// pre: 0 none, 1 rowscale, 2 logmap0, 3 l2norm    act: 0 none, 1 leaky(0.2)
// block = 128 rows x 128 cols, 256 threads, 8x8 outputs/thread via fma.rn.f32x2.
// smem: Wt transposed [k][j], row stride 132 (pad kills STS bank conflicts);
//       As [r][k], stride 128.
__device__ __forceinline__ void gemm_body(
    const float* __restrict__ A, int lda, const float* __restrict__ rowscale,
    const float* __restrict__ W, const float* __restrict__ Bias,
    float* __restrict__ C, int ldc, int pre, int act)
{
    extern __shared__ float sm[];
    float* Wt = sm;                 // 128 * 132
    float* As = sm + 128 * 132;     // 128 * 128
    int tid = threadIdx.x, warp = tid >> 5, lane = tid & 31;
    int row0 = blockIdx.x * 128;

    // W transpose: lanes write consecutive k for fixed j-pair; stride-132 rows
    // give bank = (4k + j) % 32 -> at most 4-way conflict.
    for (int idx = tid; idx < 16384; idx += 256) {
        int j = idx >> 7, k = idx & 127;
        Wt[k * 132 + j] = W[idx];
    }
    // A tile: warp loads one full row per iteration (warp_sum valid for norms)
    for (int it = 0; it < 16; it++) {
        int rl = it * 8 + warp;
        int gr = row0 + rl;
        float4 v = make_float4(0.f, 0.f, 0.f, 0.f);
        if (gr < N_NODES) {
            v = ((const float4*)(A + (size_t)gr * lda))[lane];
            if (pre == 1) {
                v = f4scale(v, rowscale[gr]);
            } else if (pre == 2) {  // logmap0
                float nb = sqrtf(warp_sum(v.x * v.x + v.y * v.y + v.z * v.z + v.w * v.w));
                float nc = fminf(fmaxf(nb, 1e-7f), 1.0f - 1e-5f);
                v = f4scale(v, atanhf(nc) / fmaxf(nb, 1e-7f));
            } else if (pre == 3) {  // l2norm
                float ns = sqrtf(warp_sum(v.x * v.x + v.y * v.y + v.z * v.z + v.w * v.w));
                v = f4scale(v, 1.0f / fmaxf(ns, 1e-12f));
            }
        }
        ((float4*)(As + rl * 128))[lane] = v;
    }
    __syncthreads();

    // per thread: rows rbase..rbase+7, cols {cbase..+3} and {cbase+64..+67}
    int rbase = warp * 16 + (lane >> 4) * 8;
    int cbase = (lane & 15) * 4;

    unsigned long long acc[8][4];
#pragma unroll
    for (int r = 0; r < 8; r++)
#pragma unroll
        for (int c = 0; c < 4; c++) acc[r][c] = 0ull;

#pragma unroll 4
    for (int k4 = 0; k4 < 32; k4++) {
        float4 a[8];
#pragma unroll
        for (int r = 0; r < 8; r++)
            a[r] = *(const float4*)(As + (rbase + r) * 128 + k4 * 4);
#pragma unroll
        for (int kk = 0; kk < 4; kk++) {
            const float* wrow = Wt + (k4 * 4 + kk) * 132;
            ulonglong2 wlo = *(const ulonglong2*)(wrow + cbase);
            ulonglong2 whi = *(const ulonglong2*)(wrow + cbase + 64);
#pragma unroll
            for (int r = 0; r < 8; r++) {
                float av = ((const float*)&a[r])[kk];
                unsigned long long as = splat2(av);
                fma2(acc[r][0], as, wlo.x);
                fma2(acc[r][1], as, wlo.y);
                fma2(acc[r][2], as, whi.x);
                fma2(acc[r][3], as, whi.y);
            }
        }
    }

    float4 blo = *(const float4*)(Bias + cbase);
    float4 bhi = *(const float4*)(Bias + cbase + 64);
#pragma unroll
    for (int r = 0; r < 8; r++) {
        int gr = row0 + rbase + r;
        if (gr >= N_NODES) continue;
        float2 p0 = unpk(acc[r][0]), p1 = unpk(acc[r][1]);
        float2 p2 = unpk(acc[r][2]), p3 = unpk(acc[r][3]);
        float4 lo = make_float4(p0.x + blo.x, p0.y + blo.y, p1.x + blo.z, p1.y + blo.w);
        float4 hi = make_float4(p2.x + bhi.x, p2.y + bhi.y, p3.x + bhi.z, p3.y + bhi.w);
        if (act) {
            lo.x = lo.x > 0.f ? lo.x : 0.2f * lo.x;
            lo.y = lo.y > 0.f ? lo.y : 0.2f * lo.y;
            lo.z = lo.z > 0.f ? lo.z : 0.2f * lo.z;
            lo.w = lo.w > 0.f ? lo.w : 0.2f * lo.w;
            hi.x = hi.x > 0.f ? hi.x : 0.2f * hi.x;
            hi.y = hi.y > 0.f ? hi.y : 0.2f * hi.y;
            hi.z = hi.z > 0.f ? hi.z : 0.2f * hi.z;
            hi.w = hi.w > 0.f ? hi.w : 0.2f * hi.w;
        }
        float* crow = C + (size_t)gr * ldc;
        *(float4*)(crow + cbase) = lo;
        *(float4*)(crow + cbase + 64) = hi;
    }
}

// combined b + s GEMM (blockIdx.y selects branch) -> writes g_feat ch1 / ch2
__global__ void __launch_bounds__(256, 1) k_gemm_bs(
    const float* __restrict__ Bin, const float* __restrict__ Sin,
    const float* __restrict__ bW, const float* __restrict__ bB,
    const float* __restrict__ sW, const float* __restrict__ sB)
{
    if (blockIdx.y == 0)
        gemm_body(Bin, D, nullptr, bW, bB, g_feat + D, CH, 2, 0);
    else
        gemm_body(Sin, D, nullptr, sW, sB, g_feat + 2 * D, CH, 3, 0);
}

// Euclidean GEMM: A = g_acce (aggregated sums), rowscale = norm_in, leaky-relu
__global__ void __launch_bounds__(256, 1) k_gemm_e(
    const float* __restrict__ W, const float* __restrict__ Bias,
    float* __restrict__ C)
{
    gemm_body(g_acce, D, g_norm_in, W, Bias, C, D, 1, 1);
}

// ---------------- CSR gather-aggregation + fused post transforms -----------------
__global__ void k_agg_post(float* __restrict__ bout, float* __restrict__ sout) {
    int node = (blockIdx.x * blockDim.x + threadIdx.x) >> 5;
    int lane = threadIdx.x & 31;
    if (node >= N_NODES) return;
    int e0 = g_off[node], e1 = g_off[node + 1];
    float4 a0 = make_float4(0.f, 0.f, 0.f, 0.f), a1 = a0, a2 = a0;
    int e = e0;
    for (; e + 4 <= e1; e += 4) {
        int i0 = g_csr[e], i1 = g_csr[e + 1], i2 = g_csr[e + 2], i3 = g_csr[e + 3];
        const float4* p0 = (const float4*)(g_feat + (size_t)i0 * CH);
        const float4* p1 = (const float4*)(g_feat + (size_t)i1 * CH);
        const float4* p2 = (const float4*)(g_feat + (size_t)i2 * CH);
        const float4* p3 = (const float4*)(g_feat + (size_t)i3 * CH);
        float4 v00 = p0[lane],      v10 = p1[lane],      v20 = p2[lane],      v30 = p3[lane];
        float4 v01 = p0[lane + 32], v11 = p1[lane + 32], v21 = p2[lane + 32], v31 = p3[lane + 32];
        float4 v02 = p0[lane + 64], v12 = p1[lane + 64], v22 = p2[lane + 64], v32 = p3[lane + 64];
        a0 = f4add(a0, f4add(f4add(v00, v10), f4add(v20, v30)));
        a1 = f4add(a1, f4add(f4add(v01, v11), f4add(v21, v31)));
        a2 = f4add(a2, f4add(f4add(v02, v12), f4add(v22, v32)));
    }
    for (; e < e1; e++) {
        const float4* p = (const float4*)(g_feat + (size_t)g_csr[e] * CH);
        a0 = f4add(a0, p[lane]);
        a1 = f4add(a1, p[lane + 32]);
        a2 = f4add(a2, p[lane + 64]);
    }
    // e channel: raw sum for the e-GEMM (norm_in applied there)
    ((float4*)(g_acce + (size_t)node * D))[lane] = a0;

    float ii = g_inv_in[node];
    // hyperbolic: expmap0(mean)
    float4 v = f4scale(a1, ii);
    float nb = sqrtf(warp_sum(v.x * v.x + v.y * v.y + v.z * v.z + v.w * v.w));
    float fb = tanhf(nb) / fmaxf(nb, 1e-7f);
    ((float4*)(bout + (size_t)node * D))[lane] = f4scale(v, fb);
    // spherical: l2norm(mean)
    float4 u = f4scale(a2, ii);
    float ns = sqrtf(warp_sum(u.x * u.x + u.y * u.y + u.z * u.z + u.w * u.w));
    float fs = 1.0f / fmaxf(ns, 1e-12f);
    ((float4*)(sout + (size_t)node * D))[lane] = f4scale(u, fs);
}

// ---------------- launch ----------------------------------------------------------
extern "C" void kernel_launch(void* const* d_in, const int* in_sizes, int n_in,
                              void* d_out, int out_size) {
    const float* e0  = (const float*)d_in[0];
    const float* b0  = (const float*)d_in[1];
    const float* s0  = (const float*)d_in[2];
    const float* eW  = (const float*)d_in[3];
    const float* eB  = (const float*)d_in[4];
    const float* bW  = (const float*)d_in[5];
    const float* bB  = (const float*)d_in[6];
    const float* sW  = (const float*)d_in[7];
    const float* sB  = (const float*)d_in[8];
    const int*   src = (const int*)d_in[9];
    const int*   dst = (const int*)d_in[10];
    float* out = (float*)d_out;

    const int SMEM_GEMM = (128 * 132 + 128 * 128) * (int)sizeof(float);  // 133120
    cudaFuncSetAttribute(k_gemm_bs, cudaFuncAttributeMaxDynamicSharedMemorySize, SMEM_GEMM);
    cudaFuncSetAttribute(k_gemm_e,  cudaFuncAttributeMaxDynamicSharedMemorySize, SMEM_GEMM);

    void* tmp;
    cudaGetSymbolAddress(&tmp, g_e); float* pe = (float*)tmp;
    cudaGetSymbolAddress(&tmp, g_b); float* pb = (float*)tmp;
    cudaGetSymbolAddress(&tmp, g_s); float* ps = (float*)tmp;

    const int node_grid = (N_NODES + 255) / 256;
    const int edge_grid = (N_EDGES + 255) / 256;
    const int warp_grid = (N_NODES + 7) / 8;            // warp-per-node
    const int vec_grid  = (N_NODES * 32 + 255) / 256;   // float4-per-thread
    const int gemm_grid = (N_NODES + 127) / 128;        // 391
    const int scan_blocks = (N_NODES + 1023) / 1024;    // 49

    k_zero<<<node_grid, 256>>>();
    k_deg<<<edge_grid, 256>>>(src, dst);
    k_scan1<<<scan_blocks, 1024>>>();
    k_scan2<<<1, 32>>>(scan_blocks);
    k_scan3<<<node_grid, 256>>>();
    k_scatter<<<edge_grid, 256>>>(src, dst);

    for (int l = 0; l < NLAYERS; l++) {
        const float* ein = (l == 0) ? e0 : pe;
        const float* bin = (l == 0) ? b0 : pb;
        const float* sin = (l == 0) ? s0 : ps;
        float* eout = (l == NLAYERS - 1) ? out                           : pe;
        float* bout = (l == NLAYERS - 1) ? out + (size_t)N_NODES * D     : pb;
        float* sout = (l == NLAYERS - 1) ? out + (size_t)2 * N_NODES * D : ps;

        k_feat_e<<<vec_grid, 256>>>(ein);
        {
            dim3 g(gemm_grid, 2);
            k_gemm_bs<<<g, 256, SMEM_GEMM>>>(bin, sin,
                                             bW + (size_t)l * D * D, bB + (size_t)l * D,
                                             sW + (size_t)l * D * D, sB + (size_t)l * D);
        }
        k_agg_post<<<warp_grid, 256>>>(bout, sout);
        k_gemm_e<<<gemm_grid, 256, SMEM_GEMM>>>(eW + (size_t)l * D * D,
                                                eB + (size_t)l * D, eout);
    }
}

// round 3
// speedup vs baseline: 1.6937x; 1.1961x over previous
#include <cuda_runtime.h>
#include <cuda_fp16.h>
#include <math.h>

#define N_NODES 50000
#define N_EDGES 800000
#define D 128
#define CHH 384  /* 3*D half channels per row: e | b | s */

// ---------------- device scratch ----------------------------------------------
static __device__ __half g_feath[(size_t)N_NODES * CHH]; // fp16 pre-agg features
static __device__ float  g_acce [(size_t)N_NODES * D];   // aggregated e sums (fp32)
static __device__ float  g_b    [(size_t)N_NODES * D];   // hyperbolic state
static __device__ float  g_s    [(size_t)N_NODES * D];   // spherical state
static __device__ int    g_indeg [N_NODES];
static __device__ int    g_outdeg[N_NODES];
static __device__ int    g_cursor[N_NODES];
static __device__ int    g_off [N_NODES + 1];
static __device__ int    g_part[64];
static __device__ int    g_csr [N_EDGES];
static __device__ float  g_norm_out[N_NODES];
static __device__ float  g_norm_in [N_NODES];
static __device__ float  g_inv_in  [N_NODES];

// ---------------- helpers -------------------------------------------------------
__device__ __forceinline__ float4 f4scale(float4 a, float s) {
    return make_float4(a.x * s, a.y * s, a.z * s, a.w * s);
}
__device__ __forceinline__ float warp_sum(float v) {
#pragma unroll
    for (int o = 16; o > 0; o >>= 1) v += __shfl_xor_sync(0xffffffffu, v, o);
    return v;
}
__device__ __forceinline__ unsigned long long splat2(float x) {
    unsigned long long r;
    asm("mov.b64 %0, {%1, %1};" : "=l"(r) : "f"(x));
    return r;
}
__device__ __forceinline__ void fma2(unsigned long long& d, unsigned long long a,
                                     unsigned long long b) {
    asm("fma.rn.f32x2 %0, %1, %2, %0;" : "+l"(d) : "l"(a), "l"(b));
}
__device__ __forceinline__ float2 unpk(unsigned long long v) {
    float2 f;
    asm("mov.b64 {%0, %1}, %2;" : "=f"(f.x), "=f"(f.y) : "l"(v));
    return f;
}
// accumulate 4 halves (packed in uint2) into float4
__device__ __forceinline__ void acc_u2(float4& a, uint2 u) {
    __half2 h0 = *reinterpret_cast<__half2*>(&u.x);
    __half2 h1 = *reinterpret_cast<__half2*>(&u.y);
    float2 f0 = __half22float2(h0), f1 = __half22float2(h1);
    a.x += f0.x; a.y += f0.y; a.z += f1.x; a.w += f1.y;
}
__device__ __forceinline__ uint2 pack_h4(float4 v) {
    __half2 h0 = __floats2half2_rn(v.x, v.y);
    __half2 h1 = __floats2half2_rn(v.z, v.w);
    uint2 r;
    r.x = *reinterpret_cast<unsigned*>(&h0);
    r.y = *reinterpret_cast<unsigned*>(&h1);
    return r;
}

// ---------------- graph preprocessing -------------------------------------------
__global__ void k_zero() {
    int i = blockIdx.x * blockDim.x + threadIdx.x;
    if (i < N_NODES) { g_indeg[i] = 0; g_outdeg[i] = 0; g_cursor[i] = 0; }
}

__global__ void k_deg(const int* __restrict__ src, const int* __restrict__ dst) {
    int e = blockIdx.x * blockDim.x + threadIdx.x;
    if (e < N_EDGES) {
        atomicAdd(&g_outdeg[src[e]], 1);
        atomicAdd(&g_indeg[dst[e]], 1);
    }
}

__global__ void k_scan1() {
    __shared__ int wsum[32];
    int tid = threadIdx.x;
    int i = blockIdx.x * 1024 + tid;
    int v = (i < N_NODES) ? g_indeg[i] : 0;
    int x = v;
#pragma unroll
    for (int o = 1; o < 32; o <<= 1) {
        int y = __shfl_up_sync(0xffffffffu, x, o);
        if ((tid & 31) >= o) x += y;
    }
    if ((tid & 31) == 31) wsum[tid >> 5] = x;
    __syncthreads();
    if (tid < 32) {
        int w = wsum[tid];
#pragma unroll
        for (int o = 1; o < 32; o <<= 1) {
            int y = __shfl_up_sync(0xffffffffu, w, o);
            if (tid >= o) w += y;
        }
        wsum[tid] = w;
    }
    __syncthreads();
    int add = (tid >= 32) ? wsum[(tid >> 5) - 1] : 0;
    if (i < N_NODES) g_off[i] = x + add - v;
    if (tid == 0) g_part[blockIdx.x] = wsum[31];
}

__global__ void k_scan2(int nblocks) {
    if (threadIdx.x == 0) {
        int run = 0;
        for (int b = 0; b < nblocks; b++) { int t = g_part[b]; g_part[b] = run; run += t; }
        g_off[N_NODES] = run;
    }
}

__global__ void k_scan3() {
    int i = blockIdx.x * blockDim.x + threadIdx.x;
    if (i < N_NODES) {
        g_off[i] += g_part[i >> 10];
        int od = g_outdeg[i], id = g_indeg[i];
        g_norm_out[i] = od > 0 ? rsqrtf((float)od) : 0.0f;
        g_norm_in[i]  = id > 0 ? rsqrtf((float)id) : 0.0f;
        g_inv_in[i]   = id > 0 ? 1.0f / (float)id : 0.0f;
    }
}

__global__ void k_scatter(const int* __restrict__ src, const int* __restrict__ dst) {
    int e = blockIdx.x * blockDim.x + threadIdx.x;
    if (e < N_EDGES) {
        int d = dst[e];
        int p = atomicAdd(&g_cursor[d], 1);
        g_csr[g_off[d] + p] = src[e];
    }
}

// ---------------- layer-0 e feature: feat ch0 = fp16(e0 * norm_out) --------------
__global__ void k_feat_e0(const float* __restrict__ e) {
    int idx = blockIdx.x * blockDim.x + threadIdx.x;  // one float4 / uint2 per thread
    if (idx >= N_NODES * (D / 4)) return;
    int node = idx >> 5;
    int c = idx & 31;
    float4 v = f4scale(((const float4*)e)[idx], g_norm_out[node]);
    ((uint2*)(g_feath + (size_t)node * CHH))[c] = pack_h4(v);
}

// ---------------- fused GEMM body -------------------------------------------------
// PRE:  0 none, 1 rowscale(norm_in), 2 logmap0, 3 l2norm
// ACT:  0 none, 1 leaky(0.2)
// MODE: 0 fp32 C (ldc=D), 1 fp16 feat at channel CHOFF
// PS:   multiply epilogue by norm_out (only with MODE=1, e-channel)
template <int PRE, int ACT, int MODE, int CHOFF, bool PS>
__device__ __forceinline__ void gemm_body(
    const float* __restrict__ A, const float* __restrict__ W,
    const float* __restrict__ Bias, float* __restrict__ C)
{
    extern __shared__ float sm[];
    float* Wt = sm;                 // [k][j], stride 132
    float* As = sm + 128 * 132;     // [r][k], stride 128
    int tid = threadIdx.x, warp = tid >> 5, lane = tid & 31;
    int row0 = blockIdx.x * 128;

    for (int idx = tid; idx < 16384; idx += 256) {
        int j = idx >> 7, k = idx & 127;
        Wt[k * 132 + j] = W[idx];
    }
    for (int it = 0; it < 16; it++) {
        int rl = it * 8 + warp;
        int gr = row0 + rl;
        float4 v = make_float4(0.f, 0.f, 0.f, 0.f);
        if (gr < N_NODES) {
            v = ((const float4*)(A + (size_t)gr * D))[lane];
            if (PRE == 1) {
                v = f4scale(v, g_norm_in[gr]);
            } else if (PRE == 2) {  // logmap0
                float nb = sqrtf(warp_sum(v.x * v.x + v.y * v.y + v.z * v.z + v.w * v.w));
                float nc = fminf(fmaxf(nb, 1e-7f), 1.0f - 1e-5f);
                v = f4scale(v, atanhf(nc) / fmaxf(nb, 1e-7f));
            } else if (PRE == 3) {  // l2norm
                float ns = sqrtf(warp_sum(v.x * v.x + v.y * v.y + v.z * v.z + v.w * v.w));
                v = f4scale(v, 1.0f / fmaxf(ns, 1e-12f));
            }
        }
        ((float4*)(As + rl * 128))[lane] = v;
    }
    __syncthreads();

    int rbase = warp * 16 + (lane >> 4) * 8;
    int cbase = (lane & 15) * 4;

    unsigned long long acc[8][4];
#pragma unroll
    for (int r = 0; r < 8; r++)
#pragma unroll
        for (int c = 0; c < 4; c++) acc[r][c] = 0ull;

#pragma unroll 4
    for (int k4 = 0; k4 < 32; k4++) {
        float4 a[8];
#pragma unroll
        for (int r = 0; r < 8; r++)
            a[r] = *(const float4*)(As + (rbase + r) * 128 + k4 * 4);
#pragma unroll
        for (int kk = 0; kk < 4; kk++) {
            const float* wrow = Wt + (k4 * 4 + kk) * 132;
            ulonglong2 wlo = *(const ulonglong2*)(wrow + cbase);
            ulonglong2 whi = *(const ulonglong2*)(wrow + cbase + 64);
#pragma unroll
            for (int r = 0; r < 8; r++) {
                unsigned long long as = splat2(((const float*)&a[r])[kk]);
                fma2(acc[r][0], as, wlo.x);
                fma2(acc[r][1], as, wlo.y);
                fma2(acc[r][2], as, whi.x);
                fma2(acc[r][3], as, whi.y);
            }
        }
    }

    float4 blo = *(const float4*)(Bias + cbase);
    float4 bhi = *(const float4*)(Bias + cbase + 64);
#pragma unroll
    for (int r = 0; r < 8; r++) {
        int gr = row0 + rbase + r;
        if (gr >= N_NODES) continue;
        float2 p0 = unpk(acc[r][0]), p1 = unpk(acc[r][1]);
        float2 p2 = unpk(acc[r][2]), p3 = unpk(acc[r][3]);
        float4 lo = make_float4(p0.x + blo.x, p0.y + blo.y, p1.x + blo.z, p1.y + blo.w);
        float4 hi = make_float4(p2.x + bhi.x, p2.y + bhi.y, p3.x + bhi.z, p3.y + bhi.w);
        if (ACT) {
            lo.x = lo.x > 0.f ? lo.x : 0.2f * lo.x;
            lo.y = lo.y > 0.f ? lo.y : 0.2f * lo.y;
            lo.z = lo.z > 0.f ? lo.z : 0.2f * lo.z;
            lo.w = lo.w > 0.f ? lo.w : 0.2f * lo.w;
            hi.x = hi.x > 0.f ? hi.x : 0.2f * hi.x;
            hi.y = hi.y > 0.f ? hi.y : 0.2f * hi.y;
            hi.z = hi.z > 0.f ? hi.z : 0.2f * hi.z;
            hi.w = hi.w > 0.f ? hi.w : 0.2f * hi.w;
        }
        if (MODE == 0) {
            float* crow = C + (size_t)gr * D;
            *(float4*)(crow + cbase) = lo;
            *(float4*)(crow + cbase + 64) = hi;
        } else {
            float sc = PS ? g_norm_out[gr] : 1.0f;
            __half* frow = g_feath + (size_t)gr * CHH + CHOFF;
            *(uint2*)(frow + cbase)      = pack_h4(f4scale(lo, sc));
            *(uint2*)(frow + cbase + 64) = pack_h4(f4scale(hi, sc));
        }
    }
}

// layer-0 b/s GEMMs -> feat ch1/ch2 (fp16)
__global__ void __launch_bounds__(256, 1) k_gemm_bs0(
    const float* __restrict__ b0, const float* __restrict__ s0,
    const float* __restrict__ bW, const float* __restrict__ bB,
    const float* __restrict__ sW, const float* __restrict__ sB)
{
    if (blockIdx.y == 0)
        gemm_body<2, 0, 1, 128, false>(b0, bW, bB, nullptr);
    else
        gemm_body<3, 0, 1, 256, false>(s0, sW, sB, nullptr);
}

// merged mid GEMMs: e-GEMM(layer0)->feat ch0, b/s GEMM(layer1)->feat ch1/2
__global__ void __launch_bounds__(256, 1) k_gemm3(
    const float* __restrict__ eW0, const float* __restrict__ eB0,
    const float* __restrict__ bW1, const float* __restrict__ bB1,
    const float* __restrict__ sW1, const float* __restrict__ sB1)
{
    if (blockIdx.y == 0)
        gemm_body<1, 1, 1, 0, true>(g_acce, eW0, eB0, nullptr);
    else if (blockIdx.y == 1)
        gemm_body<2, 0, 1, 128, false>(g_b, bW1, bB1, nullptr);
    else
        gemm_body<3, 0, 1, 256, false>(g_s, sW1, sB1, nullptr);
}

// final e-GEMM -> fp32 out
__global__ void __launch_bounds__(256, 1) k_gemm_elast(
    const float* __restrict__ W, const float* __restrict__ B, float* __restrict__ out)
{
    gemm_body<1, 1, 0, 0, false>(g_acce, W, B, out);
}

// ---------------- CSR gather-aggregation (fp16 feat) + fused post ----------------
__global__ void k_agg_post(float* __restrict__ bout, float* __restrict__ sout) {
    int node = (blockIdx.x * blockDim.x + threadIdx.x) >> 5;
    int lane = threadIdx.x & 31;
    if (node >= N_NODES) return;
    int e0 = g_off[node], e1 = g_off[node + 1];
    float4 a0 = make_float4(0.f, 0.f, 0.f, 0.f), a1 = a0, a2 = a0;
    int e = e0;
    for (; e + 4 <= e1; e += 4) {
        int i0 = g_csr[e], i1 = g_csr[e + 1], i2 = g_csr[e + 2], i3 = g_csr[e + 3];
        const uint2* p0 = (const uint2*)(g_feath + (size_t)i0 * CHH);
        const uint2* p1 = (const uint2*)(g_feath + (size_t)i1 * CHH);
        const uint2* p2 = (const uint2*)(g_feath + (size_t)i2 * CHH);
        const uint2* p3 = (const uint2*)(g_feath + (size_t)i3 * CHH);
        uint2 v00 = p0[lane],      v10 = p1[lane],      v20 = p2[lane],      v30 = p3[lane];
        uint2 v01 = p0[lane + 32], v11 = p1[lane + 32], v21 = p2[lane + 32], v31 = p3[lane + 32];
        uint2 v02 = p0[lane + 64], v12 = p1[lane + 64], v22 = p2[lane + 64], v32 = p3[lane + 64];
        acc_u2(a0, v00); acc_u2(a0, v10); acc_u2(a0, v20); acc_u2(a0, v30);
        acc_u2(a1, v01); acc_u2(a1, v11); acc_u2(a1, v21); acc_u2(a1, v31);
        acc_u2(a2, v02); acc_u2(a2, v12); acc_u2(a2, v22); acc_u2(a2, v32);
    }
    for (; e < e1; e++) {
        const uint2* p = (const uint2*)(g_feath + (size_t)g_csr[e] * CHH);
        acc_u2(a0, p[lane]);
        acc_u2(a1, p[lane + 32]);
        acc_u2(a2, p[lane + 64]);
    }
    // e channel: raw fp32 sum for the e-GEMM (norm_in applied there)
    ((float4*)(g_acce + (size_t)node * D))[lane] = a0;

    float ii = g_inv_in[node];
    // hyperbolic: expmap0(mean)
    float4 v = f4scale(a1, ii);
    float nb = sqrtf(warp_sum(v.x * v.x + v.y * v.y + v.z * v.z + v.w * v.w));
    float fb = tanhf(nb) / fmaxf(nb, 1e-7f);
    ((float4*)(bout + (size_t)node * D))[lane] = f4scale(v, fb);
    // spherical: l2norm(mean)
    float4 u = f4scale(a2, ii);
    float ns = sqrtf(warp_sum(u.x * u.x + u.y * u.y + u.z * u.z + u.w * u.w));
    float fs = 1.0f / fmaxf(ns, 1e-12f);
    ((float4*)(sout + (size_t)node * D))[lane] = f4scale(u, fs);
}

// ---------------- launch ----------------------------------------------------------
extern "C" void kernel_launch(void* const* d_in, const int* in_sizes, int n_in,
                              void* d_out, int out_size) {
    const float* e0  = (const float*)d_in[0];
    const float* b0  = (const float*)d_in[1];
    const float* s0  = (const float*)d_in[2];
    const float* eW  = (const float*)d_in[3];
    const float* eB  = (const float*)d_in[4];
    const float* bW  = (const float*)d_in[5];
    const float* bB  = (const float*)d_in[6];
    const float* sW  = (const float*)d_in[7];
    const float* sB  = (const float*)d_in[8];
    const int*   src = (const int*)d_in[9];
    const int*   dst = (const int*)d_in[10];
    float* out = (float*)d_out;

    const int SMEM_GEMM = (128 * 132 + 128 * 128) * (int)sizeof(float);  // 133120
    cudaFuncSetAttribute(k_gemm_bs0,  cudaFuncAttributeMaxDynamicSharedMemorySize, SMEM_GEMM);
    cudaFuncSetAttribute(k_gemm3,     cudaFuncAttributeMaxDynamicSharedMemorySize, SMEM_GEMM);
    cudaFuncSetAttribute(k_gemm_elast,cudaFuncAttributeMaxDynamicSharedMemorySize, SMEM_GEMM);

    void* tmp;
    cudaGetSymbolAddress(&tmp, g_b); float* pb = (float*)tmp;
    cudaGetSymbolAddress(&tmp, g_s); float* ps = (float*)tmp;

    const int node_grid = (N_NODES + 255) / 256;
    const int edge_grid = (N_EDGES + 255) / 256;
    const int warp_grid = (N_NODES + 7) / 8;
    const int vec_grid  = (N_NODES * 32 + 255) / 256;
    const int gemm_grid = (N_NODES + 127) / 128;      // 391
    const int scan_blocks = (N_NODES + 1023) / 1024;  // 49

    // preprocessing
    k_zero<<<node_grid, 256>>>();
    k_deg<<<edge_grid, 256>>>(src, dst);
    k_scan1<<<scan_blocks, 1024>>>();
    k_scan2<<<1, 32>>>(scan_blocks);
    k_scan3<<<node_grid, 256>>>();
    k_scatter<<<edge_grid, 256>>>(src, dst);

    // layer 0 features
    k_feat_e0<<<vec_grid, 256>>>(e0);
    {
        dim3 g(gemm_grid, 2);
        k_gemm_bs0<<<g, 256, SMEM_GEMM>>>(b0, s0, bW, bB, sW, sB);
    }
    // layer 0 aggregation (+ b/s post) -> g_acce, pb, ps
    k_agg_post<<<warp_grid, 256>>>(pb, ps);
    // e-GEMM(l0)->feat ch0 ; b/s-GEMM(l1)->feat ch1/2  (merged)
    {
        dim3 g(gemm_grid, 3);
        k_gemm3<<<g, 256, SMEM_GEMM>>>(eW, eB,
                                       bW + (size_t)D * D, bB + D,
                                       sW + (size_t)D * D, sB + D);
    }
    // layer 1 aggregation (+ final b/s outputs)
    k_agg_post<<<warp_grid, 256>>>(out + (size_t)N_NODES * D,
                                   out + (size_t)2 * N_NODES * D);
    // final e-GEMM -> out
    k_gemm_elast<<<gemm_grid, 256, SMEM_GEMM>>>(eW + (size_t)D * D, eB + D, out);
}

// round 6
// speedup vs baseline: 3.2281x; 1.9060x over previous
#include <cuda_runtime.h>
#include <cuda_fp16.h>
#include <cstdint>
#include <math.h>

#define N_NODES 50000
#define N_EDGES 800000
#define D 128
#define CHH 384  /* 3*D half channels per row: e | b | s */
#define SP 136   /* smem row stride in halves (272B) */

// ---------------- device scratch ----------------------------------------------
static __device__ __half g_feath[(size_t)N_NODES * CHH]; // fp16 pre-agg features
static __device__ float  g_acce [(size_t)N_NODES * D];   // aggregated e sums (fp32)
static __device__ float  g_b    [(size_t)N_NODES * D];
static __device__ float  g_s    [(size_t)N_NODES * D];
static __device__ int    g_indeg [N_NODES];
static __device__ int    g_outdeg[N_NODES];
static __device__ int    g_cursor[N_NODES];
static __device__ int    g_off [N_NODES + 1];
static __device__ int    g_part[64];
static __device__ int    g_csr [N_EDGES];
static __device__ float  g_norm_out[N_NODES];
static __device__ float  g_norm_in [N_NODES];
static __device__ float  g_inv_in  [N_NODES];

// ---------------- helpers -------------------------------------------------------
__device__ __forceinline__ float4 f4scale(float4 a, float s) {
    return make_float4(a.x * s, a.y * s, a.z * s, a.w * s);
}
__device__ __forceinline__ float warp_sum(float v) {
#pragma unroll
    for (int o = 16; o > 0; o >>= 1) v += __shfl_xor_sync(0xffffffffu, v, o);
    return v;
}
__device__ __forceinline__ void acc_u2(float4& a, uint2 u) {
    __half2 h0 = *reinterpret_cast<__half2*>(&u.x);
    __half2 h1 = *reinterpret_cast<__half2*>(&u.y);
    float2 f0 = __half22float2(h0), f1 = __half22float2(h1);
    a.x += f0.x; a.y += f0.y; a.z += f1.x; a.w += f1.y;
}
__device__ __forceinline__ uint2 pack_h4(float4 v) {
    __half2 h0 = __floats2half2_rn(v.x, v.y);
    __half2 h1 = __floats2half2_rn(v.z, v.w);
    uint2 r;
    r.x = *reinterpret_cast<unsigned*>(&h0);
    r.y = *reinterpret_cast<unsigned*>(&h1);
    return r;
}
__device__ __forceinline__ uint32_t smem_u32(const void* p) {
    uint32_t a;
    asm("{ .reg .u64 t; cvta.to.shared.u64 t, %1; cvt.u32.u64 %0, t; }" : "=r"(a) : "l"(p));
    return a;
}
__device__ __forceinline__ void ldsm4(uint32_t* r, uint32_t addr) {
    asm volatile("ldmatrix.sync.aligned.m8n8.x4.shared.b16 {%0,%1,%2,%3}, [%4];"
                 : "=r"(r[0]), "=r"(r[1]), "=r"(r[2]), "=r"(r[3]) : "r"(addr));
}
__device__ __forceinline__ void mma16816(float* c, const uint32_t* a, uint32_t b0, uint32_t b1) {
    asm volatile(
        "mma.sync.aligned.m16n8k16.row.col.f32.f16.f16.f32 "
        "{%0,%1,%2,%3}, {%4,%5,%6,%7}, {%8,%9}, {%0,%1,%2,%3};"
        : "+f"(c[0]), "+f"(c[1]), "+f"(c[2]), "+f"(c[3])
        : "r"(a[0]), "r"(a[1]), "r"(a[2]), "r"(a[3]), "r"(b0), "r"(b1));
}

// ---------------- graph preprocessing -------------------------------------------
__global__ void k_zero() {
    int i = blockIdx.x * blockDim.x + threadIdx.x;
    if (i < N_NODES) { g_indeg[i] = 0; g_outdeg[i] = 0; g_cursor[i] = 0; }
}

__global__ void k_deg(const int* __restrict__ src, const int* __restrict__ dst) {
    int e = blockIdx.x * blockDim.x + threadIdx.x;
    if (e < N_EDGES) {
        atomicAdd(&g_outdeg[src[e]], 1);
        atomicAdd(&g_indeg[dst[e]], 1);
    }
}

__global__ void k_scan1() {
    __shared__ int wsum[32];
    int tid = threadIdx.x;
    int i = blockIdx.x * 1024 + tid;
    int v = (i < N_NODES) ? g_indeg[i] : 0;
    int x = v;
#pragma unroll
    for (int o = 1; o < 32; o <<= 1) {
        int y = __shfl_up_sync(0xffffffffu, x, o);
        if ((tid & 31) >= o) x += y;
    }
    if ((tid & 31) == 31) wsum[tid >> 5] = x;
    __syncthreads();
    if (tid < 32) {
        int w = wsum[tid];
#pragma unroll
        for (int o = 1; o < 32; o <<= 1) {
            int y = __shfl_up_sync(0xffffffffu, w, o);
            if (tid >= o) w += y;
        }
        wsum[tid] = w;
    }
    __syncthreads();
    int add = (tid >= 32) ? wsum[(tid >> 5) - 1] : 0;
    if (i < N_NODES) g_off[i] = x + add - v;
    if (tid == 0) g_part[blockIdx.x] = wsum[31];
}

__global__ void k_scan3() {
    __shared__ int pref;
    int i = blockIdx.x * blockDim.x + threadIdx.x;
    if (threadIdx.x == 0) {
        int gb = blockIdx.x >> 2;
        int s = 0;
        for (int t = 0; t < gb; t++) s += g_part[t];
        pref = s;
    }
    __syncthreads();
    if (i < N_NODES) {
        g_off[i] += pref;
        int od = g_outdeg[i], id = g_indeg[i];
        g_norm_out[i] = od > 0 ? rsqrtf((float)od) : 0.0f;
        g_norm_in[i]  = id > 0 ? rsqrtf((float)id) : 0.0f;
        g_inv_in[i]   = id > 0 ? 1.0f / (float)id : 0.0f;
    }
    if (i == 0) g_off[N_NODES] = N_EDGES;
}

__global__ void k_scatter(const int* __restrict__ src, const int* __restrict__ dst) {
    int e = blockIdx.x * blockDim.x + threadIdx.x;
    if (e < N_EDGES) {
        int d = dst[e];
        int p = atomicAdd(&g_cursor[d], 1);
        g_csr[g_off[d] + p] = src[e];
    }
}

// ---------------- layer-0 e feature: feat ch0 = fp16(e0 * norm_out) --------------
__global__ void k_feat_e0(const float* __restrict__ e) {
    int idx = blockIdx.x * blockDim.x + threadIdx.x;
    if (idx >= N_NODES * (D / 4)) return;
    int node = idx >> 5;
    int c = idx & 31;
    float4 v = f4scale(((const float4*)e)[idx], g_norm_out[node]);
    ((uint2*)(g_feath + (size_t)node * CHH))[c] = pack_h4(v);
}

// ---------------- mma.sync fp16 GEMM body -----------------------------------------
// C[row,0:128] = act( pre(A[row,:]) @ W^T + Bias )
// PRE:  1 rowscale(norm_in), 2 logmap0, 3 l2norm
// MODE: 0 fp32 C (ldc=D), 1 fp16 feat at channel CHOFF (PS: *norm_out)
template <int PRE, int ACT, int MODE, int CHOFF, bool PS>
__device__ __forceinline__ void gemm_mma_body(
    const float* __restrict__ A, const float* __restrict__ W,
    const float* __restrict__ Bias, float* __restrict__ C)
{
    extern __shared__ __half smh[];
    __half* As = smh;             // 128 x SP
    __half* Ws = smh + 128 * SP;  // 128 x SP  (W[j][k], j rows)
    int tid = threadIdx.x, warp = tid >> 5, lane = tid & 31;
    int row0 = blockIdx.x * 128;

    // W -> fp16 smem (row-major [out j][in k])
    const float4* Wv = (const float4*)W;
#pragma unroll
    for (int it = 0; it < 16; it++) {
        int q = it * 256 + tid;
        int j = q >> 5, k4 = q & 31;
        *(uint2*)(Ws + j * SP + k4 * 4) = pack_h4(Wv[q]);
    }
    // A -> pre-transform -> fp16 smem (warp owns a full row per iter; warp_sum valid)
#pragma unroll
    for (int it = 0; it < 16; it++) {
        int rl = it * 8 + warp;
        int gr = row0 + rl;
        float4 v = make_float4(0.f, 0.f, 0.f, 0.f);
        if (gr < N_NODES) {
            v = ((const float4*)(A + (size_t)gr * D))[lane];
            if (PRE == 1) {
                v = f4scale(v, g_norm_in[gr]);
            } else if (PRE == 2) {  // logmap0
                float nb = sqrtf(warp_sum(v.x * v.x + v.y * v.y + v.z * v.z + v.w * v.w));
                float nc = fminf(fmaxf(nb, 1e-7f), 1.0f - 1e-5f);
                v = f4scale(v, atanhf(nc) / fmaxf(nb, 1e-7f));
            } else if (PRE == 3) {  // l2norm
                float ns = sqrtf(warp_sum(v.x * v.x + v.y * v.y + v.z * v.z + v.w * v.w));
                v = f4scale(v, 1.0f / fmaxf(ns, 1e-12f));
            }
        }
        *(uint2*)(As + rl * SP + lane * 4) = pack_h4(v);
    }
    __syncthreads();

    // warp tile: rows rbase..+31, cols cbase..+63
    int rbase = (warp & 3) * 32;
    int cbase = (warp >> 2) * 64;
    uint32_t sa = smem_u32(As);
    uint32_t sw = smem_u32(Ws);

    float acc[2][8][4];
#pragma unroll
    for (int mt = 0; mt < 2; mt++)
#pragma unroll
        for (int nt = 0; nt < 8; nt++)
#pragma unroll
            for (int q = 0; q < 4; q++) acc[mt][nt][q] = 0.f;

    // A frag addr: rows rbase+mt*16+(lane&15), k = ks*16 + (lane>>4)*8
    // B frag addr: j = cbase+np*16+(lane&7)+((lane>>4)&1)*8, k = ks*16 + ((lane>>3)&1)*8
    int a_row = rbase + (lane & 15);
    int a_koff = (lane >> 4) * 8;
    int b_j = cbase + (lane & 7) + ((lane >> 4) & 1) * 8;
    int b_koff = ((lane >> 3) & 1) * 8;

#pragma unroll
    for (int ks = 0; ks < 8; ks++) {
        uint32_t a[2][4];
#pragma unroll
        for (int mt = 0; mt < 2; mt++)
            ldsm4(a[mt], sa + ((a_row + mt * 16) * SP + ks * 16 + a_koff) * 2);
        uint32_t b[4][4];
#pragma unroll
        for (int np = 0; np < 4; np++)
            ldsm4(b[np], sw + ((b_j + np * 16) * SP + ks * 16 + b_koff) * 2);
#pragma unroll
        for (int mt = 0; mt < 2; mt++)
#pragma unroll
            for (int nt = 0; nt < 8; nt++)
                mma16816(acc[mt][nt], a[mt], b[nt >> 1][(nt & 1) * 2], b[nt >> 1][(nt & 1) * 2 + 1]);
    }

    // epilogue: thread t -> rows rbase+mt*16+(t/4)+{0,8}, cols cbase+nt*8+(t%4)*2
#pragma unroll
    for (int mt = 0; mt < 2; mt++) {
#pragma unroll
        for (int half = 0; half < 2; half++) {
            int gr = row0 + rbase + mt * 16 + (lane >> 2) + half * 8;
            if (gr >= N_NODES) continue;
            float sc = (MODE == 1 && PS) ? g_norm_out[gr] : 1.0f;
#pragma unroll
            for (int nt = 0; nt < 8; nt++) {
                int col = cbase + nt * 8 + (lane & 3) * 2;
                float x = acc[mt][nt][half * 2 + 0] + Bias[col];
                float y = acc[mt][nt][half * 2 + 1] + Bias[col + 1];
                if (ACT) {
                    x = x > 0.f ? x : 0.2f * x;
                    y = y > 0.f ? y : 0.2f * y;
                }
                if (MODE == 0) {
                    *(float2*)(C + (size_t)gr * D + col) = make_float2(x, y);
                } else {
                    __half2 h = __floats2half2_rn(x * sc, y * sc);
                    *(__half2*)(g_feath + (size_t)gr * CHH + CHOFF + col) = h;
                }
            }
        }
    }
}

// layer-0 b/s GEMMs -> feat ch1/ch2
__global__ void __launch_bounds__(256, 2) k_gemm_bs0(
    const float* __restrict__ b0, const float* __restrict__ s0,
    const float* __restrict__ bW, const float* __restrict__ bB,
    const float* __restrict__ sW, const float* __restrict__ sB)
{
    if (blockIdx.y == 0)
        gemm_mma_body<2, 0, 1, 128, false>(b0, bW, bB, nullptr);
    else
        gemm_mma_body<3, 0, 1, 256, false>(s0, sW, sB, nullptr);
}

// merged mid GEMMs: e-GEMM(l0)->feat ch0, b/s GEMM(l1)->feat ch1/2
__global__ void __launch_bounds__(256, 2) k_gemm3(
    const float* __restrict__ eW0, const float* __restrict__ eB0,
    const float* __restrict__ bW1, const float* __restrict__ bB1,
    const float* __restrict__ sW1, const float* __restrict__ sB1)
{
    if (blockIdx.y == 0)
        gemm_mma_body<1, 1, 1, 0, true>(g_acce, eW0, eB0, nullptr);
    else if (blockIdx.y == 1)
        gemm_mma_body<2, 0, 1, 128, false>(g_b, bW1, bB1, nullptr);
    else
        gemm_mma_body<3, 0, 1, 256, false>(g_s, sW1, sB1, nullptr);
}

// final e-GEMM -> fp32 out
__global__ void __launch_bounds__(256, 2) k_gemm_elast(
    const float* __restrict__ W, const float* __restrict__ B, float* __restrict__ out)
{
    gemm_mma_body<1, 1, 0, 0, false>(g_acce, W, B, out);
}

// ---------------- CSR gather-aggregation (fp16 feat) + fused post ----------------
__global__ void k_agg_post(float* __restrict__ bout, float* __restrict__ sout) {
    int node = (blockIdx.x * blockDim.x + threadIdx.x) >> 5;
    int lane = threadIdx.x & 31;
    if (node >= N_NODES) return;
    int e0 = g_off[node], e1 = g_off[node + 1];
    float4 a0 = make_float4(0.f, 0.f, 0.f, 0.f), a1 = a0, a2 = a0;
    int e = e0;
    for (; e + 4 <= e1; e += 4) {
        int i0 = g_csr[e], i1 = g_csr[e + 1], i2 = g_csr[e + 2], i3 = g_csr[e + 3];
        const uint2* p0 = (const uint2*)(g_feath + (size_t)i0 * CHH);
        const uint2* p1 = (const uint2*)(g_feath + (size_t)i1 * CHH);
        const uint2* p2 = (const uint2*)(g_feath + (size_t)i2 * CHH);
        const uint2* p3 = (const uint2*)(g_feath + (size_t)i3 * CHH);
        uint2 v00 = p0[lane],      v10 = p1[lane],      v20 = p2[lane],      v30 = p3[lane];
        uint2 v01 = p0[lane + 32], v11 = p1[lane + 32], v21 = p2[lane + 32], v31 = p3[lane + 32];
        uint2 v02 = p0[lane + 64], v12 = p1[lane + 64], v22 = p2[lane + 64], v32 = p3[lane + 64];
        acc_u2(a0, v00); acc_u2(a0, v10); acc_u2(a0, v20); acc_u2(a0, v30);
        acc_u2(a1, v01); acc_u2(a1, v11); acc_u2(a1, v21); acc_u2(a1, v31);
        acc_u2(a2, v02); acc_u2(a2, v12); acc_u2(a2, v22); acc_u2(a2, v32);
    }
    for (; e < e1; e++) {
        const uint2* p = (const uint2*)(g_feath + (size_t)g_csr[e] * CHH);
        acc_u2(a0, p[lane]);
        acc_u2(a1, p[lane + 32]);
        acc_u2(a2, p[lane + 64]);
    }
    ((float4*)(g_acce + (size_t)node * D))[lane] = a0;

    float ii = g_inv_in[node];
    float4 v = f4scale(a1, ii);
    float nb = sqrtf(warp_sum(v.x * v.x + v.y * v.y + v.z * v.z + v.w * v.w));
    float fb = tanhf(nb) / fmaxf(nb, 1e-7f);
    ((float4*)(bout + (size_t)node * D))[lane] = f4scale(v, fb);
    float4 u = f4scale(a2, ii);
    float ns = sqrtf(warp_sum(u.x * u.x + u.y * u.y + u.z * u.z + u.w * u.w));
    float fs = 1.0f / fmaxf(ns, 1e-12f);
    ((float4*)(sout + (size_t)node * D))[lane] = f4scale(u, fs);
}

// ---------------- launch ----------------------------------------------------------
extern "C" void kernel_launch(void* const* d_in, const int* in_sizes, int n_in,
                              void* d_out, int out_size) {
    const float* e0  = (const float*)d_in[0];
    const float* b0  = (const float*)d_in[1];
    const float* s0  = (const float*)d_in[2];
    const float* eW  = (const float*)d_in[3];
    const float* eB  = (const float*)d_in[4];
    const float* bW  = (const float*)d_in[5];
    const float* bB  = (const float*)d_in[6];
    const float* sW  = (const float*)d_in[7];
    const float* sB  = (const float*)d_in[8];
    const int*   src = (const int*)d_in[9];
    const int*   dst = (const int*)d_in[10];
    float* out = (float*)d_out;

    const int SMEM_GEMM = 2 * 128 * SP * (int)sizeof(__half);  // 69632
    cudaFuncSetAttribute(k_gemm_bs0,   cudaFuncAttributeMaxDynamicSharedMemorySize, SMEM_GEMM);
    cudaFuncSetAttribute(k_gemm3,      cudaFuncAttributeMaxDynamicSharedMemorySize, SMEM_GEMM);
    cudaFuncSetAttribute(k_gemm_elast, cudaFuncAttributeMaxDynamicSharedMemorySize, SMEM_GEMM);

    void* tmp;
    cudaGetSymbolAddress(&tmp, g_b); float* pb = (float*)tmp;
    cudaGetSymbolAddress(&tmp, g_s); float* ps = (float*)tmp;

    const int node_grid = (N_NODES + 255) / 256;
    const int edge_grid = (N_EDGES + 255) / 256;
    const int warp_grid = (N_NODES + 7) / 8;
    const int vec_grid  = (N_NODES * 32 + 255) / 256;
    const int gemm_grid = (N_NODES + 127) / 128;      // 391
    const int scan_blocks = (N_NODES + 1023) / 1024;  // 49

    // preprocessing
    k_zero<<<node_grid, 256>>>();
    k_deg<<<edge_grid, 256>>>(src, dst);
    k_scan1<<<scan_blocks, 1024>>>();
    k_scan3<<<node_grid, 256>>>();
    k_scatter<<<edge_grid, 256>>>(src, dst);

    // layer 0 features
    k_feat_e0<<<vec_grid, 256>>>(e0);
    {
        dim3 g(gemm_grid, 2);
        k_gemm_bs0<<<g, 256, SMEM_GEMM>>>(b0, s0, bW, bB, sW, sB);
    }
    // layer 0 aggregation (+ b/s post)
    k_agg_post<<<warp_grid, 256>>>(pb, ps);
    // e-GEMM(l0)->feat ch0 ; b/s-GEMM(l1)->feat ch1/2
    {
        dim3 g(gemm_grid, 3);
        k_gemm3<<<g, 256, SMEM_GEMM>>>(eW, eB,
                                       bW + (size_t)D * D, bB + D,
                                       sW + (size_t)D * D, sB + D);
    }
    // layer 1 aggregation (+ final b/s outputs)
    k_agg_post<<<warp_grid, 256>>>(out + (size_t)N_NODES * D,
                                   out + (size_t)2 * N_NODES * D);
    // final e-GEMM -> out
    k_gemm_elast<<<gemm_grid, 256, SMEM_GEMM>>>(eW + (size_t)D * D, eB + D, out);
}

// round 7
// speedup vs baseline: 3.2936x; 1.0203x over previous
#include <cuda_runtime.h>
#include <cuda_fp16.h>
#include <cstdint>
#include <math.h>

#define N_NODES 50000
#define N_EDGES 800000
#define D 128
#define CHH 384  /* 3*D half channels per row: e | b | s */
#define SP 136   /* smem row stride in halves (272B) */
#define SCAN_BLOCKS 49

// ---------------- device scratch ----------------------------------------------
static __device__ __half g_feath[(size_t)N_NODES * CHH]; // fp16 pre-agg features
static __device__ float  g_acce [(size_t)N_NODES * D];   // aggregated e sums (fp32)
static __device__ float  g_b    [(size_t)N_NODES * D];
static __device__ float  g_s    [(size_t)N_NODES * D];
static __device__ int    g_indeg [N_NODES];
static __device__ int    g_outdeg[N_NODES];
static __device__ int    g_cursor[N_NODES];
static __device__ int    g_off [N_NODES + 1];
static __device__ int    g_lb  [64];                     // lookback flags (total+1)
static __device__ int    g_csr [N_EDGES];
static __device__ float  g_norm_out[N_NODES];
static __device__ float  g_norm_in [N_NODES];
static __device__ float  g_inv_in  [N_NODES];

// ---------------- helpers -------------------------------------------------------
__device__ __forceinline__ float4 f4scale(float4 a, float s) {
    return make_float4(a.x * s, a.y * s, a.z * s, a.w * s);
}
__device__ __forceinline__ float warp_sum(float v) {
#pragma unroll
    for (int o = 16; o > 0; o >>= 1) v += __shfl_xor_sync(0xffffffffu, v, o);
    return v;
}
__device__ __forceinline__ void acc_u2(float4& a, uint2 u) {
    __half2 h0 = *reinterpret_cast<__half2*>(&u.x);
    __half2 h1 = *reinterpret_cast<__half2*>(&u.y);
    float2 f0 = __half22float2(h0), f1 = __half22float2(h1);
    a.x += f0.x; a.y += f0.y; a.z += f1.x; a.w += f1.y;
}
__device__ __forceinline__ uint2 pack_h4(float4 v) {
    __half2 h0 = __floats2half2_rn(v.x, v.y);
    __half2 h1 = __floats2half2_rn(v.z, v.w);
    uint2 r;
    r.x = *reinterpret_cast<unsigned*>(&h0);
    r.y = *reinterpret_cast<unsigned*>(&h1);
    return r;
}
__device__ __forceinline__ uint32_t smem_u32(const void* p) {
    uint32_t a;
    asm("{ .reg .u64 t; cvta.to.shared.u64 t, %1; cvt.u32.u64 %0, t; }" : "=r"(a) : "l"(p));
    return a;
}
__device__ __forceinline__ void ldsm4(uint32_t* r, uint32_t addr) {
    asm volatile("ldmatrix.sync.aligned.m8n8.x4.shared.b16 {%0,%1,%2,%3}, [%4];"
                 : "=r"(r[0]), "=r"(r[1]), "=r"(r[2]), "=r"(r[3]) : "r"(addr));
}
__device__ __forceinline__ void mma16816(float* c, const uint32_t* a, uint32_t b0, uint32_t b1) {
    asm volatile(
        "mma.sync.aligned.m16n8k16.row.col.f32.f16.f16.f32 "
        "{%0,%1,%2,%3}, {%4,%5,%6,%7}, {%8,%9}, {%0,%1,%2,%3};"
        : "+f"(c[0]), "+f"(c[1]), "+f"(c[2]), "+f"(c[3])
        : "r"(a[0]), "r"(a[1]), "r"(a[2]), "r"(a[3]), "r"(b0), "r"(b1));
}

// ---------------- graph preprocessing -------------------------------------------
__global__ void k_zero() {
    int i = blockIdx.x * blockDim.x + threadIdx.x;
    if (i < N_NODES) { g_indeg[i] = 0; g_outdeg[i] = 0; g_cursor[i] = 0; }
    if (i < 64) g_lb[i] = 0;
}

__global__ void k_deg(const int* __restrict__ src, const int* __restrict__ dst) {
    int e = blockIdx.x * blockDim.x + threadIdx.x;
    if (e < N_EDGES) {
        atomicAdd(&g_outdeg[src[e]], 1);
        atomicAdd(&g_indeg[dst[e]], 1);
    }
}

// single fused scan: local block scan + parallel lookback + scales
__global__ void k_scan_all() {
    __shared__ int wsum[32];
    __shared__ int sh_prev;
    int tid = threadIdx.x;
    int i = blockIdx.x * 1024 + tid;
    int v = (i < N_NODES) ? g_indeg[i] : 0;
    int x = v;
#pragma unroll
    for (int o = 1; o < 32; o <<= 1) {
        int y = __shfl_up_sync(0xffffffffu, x, o);
        if ((tid & 31) >= o) x += y;
    }
    if ((tid & 31) == 31) wsum[tid >> 5] = x;
    __syncthreads();
    if (tid < 32) {
        int w = wsum[tid];
#pragma unroll
        for (int o = 1; o < 32; o <<= 1) {
            int y = __shfl_up_sync(0xffffffffu, w, o);
            if (tid >= o) w += y;
        }
        wsum[tid] = w;
    }
    if (tid == 0) sh_prev = 0;
    __syncthreads();
    int total = wsum[31];
    // publish this block's total (flag = total+1, 0 = not ready)
    if (tid == 0) *(volatile int*)&g_lb[blockIdx.x] = total + 1;
    // parallel lookback: thread t < blockIdx.x spins on flag[t]
    if (tid < blockIdx.x) {
        int f;
        do { f = *(volatile int*)&g_lb[tid]; } while (f == 0);
        atomicAdd(&sh_prev, f - 1);
    }
    __syncthreads();
    int add = (tid >= 32) ? wsum[(tid >> 5) - 1] : 0;
    if (i < N_NODES) {
        g_off[i] = sh_prev + x + add - v;  // global exclusive prefix
        int od = g_outdeg[i], id = g_indeg[i];
        g_norm_out[i] = od > 0 ? rsqrtf((float)od) : 0.0f;
        g_norm_in[i]  = id > 0 ? rsqrtf((float)id) : 0.0f;
        g_inv_in[i]   = id > 0 ? 1.0f / (float)id : 0.0f;
    }
    if (i == 0) g_off[N_NODES] = N_EDGES;
}

__global__ void k_scatter(const int* __restrict__ src, const int* __restrict__ dst) {
    int e = blockIdx.x * blockDim.x + threadIdx.x;
    if (e < N_EDGES) {
        int d = dst[e];
        int p = atomicAdd(&g_cursor[d], 1);
        g_csr[g_off[d] + p] = src[e];
    }
}

// ---------------- mma.sync fp16 GEMM body -----------------------------------------
// C[row,0:128] = act( pre(A[row,:]) @ W^T + Bias )
// PRE:  1 rowscale(norm_in), 2 logmap0, 3 l2norm
// MODE: 0 fp32 C (ldc=D), 1 fp16 feat at channel CHOFF (PS: *norm_out)
template <int PRE, int ACT, int MODE, int CHOFF, bool PS>
__device__ __forceinline__ void gemm_mma_body(
    const float* __restrict__ A, const float* __restrict__ W,
    const float* __restrict__ Bias, float* __restrict__ C)
{
    extern __shared__ __half smh[];
    __half* As = smh;             // 128 x SP
    __half* Ws = smh + 128 * SP;  // 128 x SP  (W[j][k], j rows)
    int tid = threadIdx.x, warp = tid >> 5, lane = tid & 31;
    int row0 = blockIdx.x * 128;

    // W -> fp16 smem (row-major [out j][in k])
    const float4* Wv = (const float4*)W;
#pragma unroll
    for (int it = 0; it < 16; it++) {
        int q = it * 256 + tid;
        int j = q >> 5, k4 = q & 31;
        *(uint2*)(Ws + j * SP + k4 * 4) = pack_h4(Wv[q]);
    }
    // A -> pre-transform -> fp16 smem (warp owns a full row per iter; warp_sum valid)
#pragma unroll
    for (int it = 0; it < 16; it++) {
        int rl = it * 8 + warp;
        int gr = row0 + rl;
        float4 v = make_float4(0.f, 0.f, 0.f, 0.f);
        if (gr < N_NODES) {
            v = ((const float4*)(A + (size_t)gr * D))[lane];
            if (PRE == 1) {
                v = f4scale(v, g_norm_in[gr]);
            } else if (PRE == 2) {  // logmap0
                float nb = sqrtf(warp_sum(v.x * v.x + v.y * v.y + v.z * v.z + v.w * v.w));
                float nc = fminf(fmaxf(nb, 1e-7f), 1.0f - 1e-5f);
                v = f4scale(v, atanhf(nc) / fmaxf(nb, 1e-7f));
            } else if (PRE == 3) {  // l2norm
                float ns = sqrtf(warp_sum(v.x * v.x + v.y * v.y + v.z * v.z + v.w * v.w));
                v = f4scale(v, 1.0f / fmaxf(ns, 1e-12f));
            }
        }
        *(uint2*)(As + rl * SP + lane * 4) = pack_h4(v);
    }
    __syncthreads();

    // warp tile: rows rbase..+31, cols cbase..+63
    int rbase = (warp & 3) * 32;
    int cbase = (warp >> 2) * 64;
    uint32_t sa = smem_u32(As);
    uint32_t sw = smem_u32(Ws);

    float acc[2][8][4];
#pragma unroll
    for (int mt = 0; mt < 2; mt++)
#pragma unroll
        for (int nt = 0; nt < 8; nt++)
#pragma unroll
            for (int q = 0; q < 4; q++) acc[mt][nt][q] = 0.f;

    int a_row = rbase + (lane & 15);
    int a_koff = (lane >> 4) * 8;
    int b_j = cbase + (lane & 7) + ((lane >> 4) & 1) * 8;
    int b_koff = ((lane >> 3) & 1) * 8;

#pragma unroll
    for (int ks = 0; ks < 8; ks++) {
        uint32_t a[2][4];
#pragma unroll
        for (int mt = 0; mt < 2; mt++)
            ldsm4(a[mt], sa + ((a_row + mt * 16) * SP + ks * 16 + a_koff) * 2);
        uint32_t b[4][4];
#pragma unroll
        for (int np = 0; np < 4; np++)
            ldsm4(b[np], sw + ((b_j + np * 16) * SP + ks * 16 + b_koff) * 2);
#pragma unroll
        for (int mt = 0; mt < 2; mt++)
#pragma unroll
            for (int nt = 0; nt < 8; nt++)
                mma16816(acc[mt][nt], a[mt], b[nt >> 1][(nt & 1) * 2], b[nt >> 1][(nt & 1) * 2 + 1]);
    }

#pragma unroll
    for (int mt = 0; mt < 2; mt++) {
#pragma unroll
        for (int half = 0; half < 2; half++) {
            int gr = row0 + rbase + mt * 16 + (lane >> 2) + half * 8;
            if (gr >= N_NODES) continue;
            float sc = (MODE == 1 && PS) ? g_norm_out[gr] : 1.0f;
#pragma unroll
            for (int nt = 0; nt < 8; nt++) {
                int col = cbase + nt * 8 + (lane & 3) * 2;
                float x = acc[mt][nt][half * 2 + 0] + Bias[col];
                float y = acc[mt][nt][half * 2 + 1] + Bias[col + 1];
                if (ACT) {
                    x = x > 0.f ? x : 0.2f * x;
                    y = y > 0.f ? y : 0.2f * y;
                }
                if (MODE == 0) {
                    *(float2*)(C + (size_t)gr * D + col) = make_float2(x, y);
                } else {
                    __half2 h = __floats2half2_rn(x * sc, y * sc);
                    *(__half2*)(g_feath + (size_t)gr * CHH + CHOFF + col) = h;
                }
            }
        }
    }
}

// layer-0: y=0 b-GEMM -> feat ch1, y=1 s-GEMM -> feat ch2, y=2 e feat copy -> ch0
__global__ void __launch_bounds__(256, 2) k_gemm_bs0(
    const float* __restrict__ e0,
    const float* __restrict__ b0, const float* __restrict__ s0,
    const float* __restrict__ bW, const float* __restrict__ bB,
    const float* __restrict__ sW, const float* __restrict__ sB)
{
    if (blockIdx.y == 0) {
        gemm_mma_body<2, 0, 1, 128, false>(b0, bW, bB, nullptr);
    } else if (blockIdx.y == 1) {
        gemm_mma_body<3, 0, 1, 256, false>(s0, sW, sB, nullptr);
    } else {
        // feat ch0 = fp16(e0 * norm_out) for rows row0..row0+127
        int row0 = blockIdx.x * 128;
        int tid = threadIdx.x;
#pragma unroll
        for (int it = 0; it < 16; it++) {
            int q = it * 256 + tid;
            int rl = q >> 5, c = q & 31;
            int gr = row0 + rl;
            if (gr < N_NODES) {
                float4 v = f4scale(((const float4*)(e0 + (size_t)gr * D))[c], g_norm_out[gr]);
                ((uint2*)(g_feath + (size_t)gr * CHH))[c] = pack_h4(v);
            }
        }
    }
}

// merged mid GEMMs: e-GEMM(l0)->feat ch0, b/s GEMM(l1)->feat ch1/2
__global__ void __launch_bounds__(256, 2) k_gemm3(
    const float* __restrict__ eW0, const float* __restrict__ eB0,
    const float* __restrict__ bW1, const float* __restrict__ bB1,
    const float* __restrict__ sW1, const float* __restrict__ sB1)
{
    if (blockIdx.y == 0)
        gemm_mma_body<1, 1, 1, 0, true>(g_acce, eW0, eB0, nullptr);
    else if (blockIdx.y == 1)
        gemm_mma_body<2, 0, 1, 128, false>(g_b, bW1, bB1, nullptr);
    else
        gemm_mma_body<3, 0, 1, 256, false>(g_s, sW1, sB1, nullptr);
}

// final e-GEMM -> fp32 out
__global__ void __launch_bounds__(256, 2) k_gemm_elast(
    const float* __restrict__ W, const float* __restrict__ B, float* __restrict__ out)
{
    gemm_mma_body<1, 1, 0, 0, false>(g_acce, W, B, out);
}

// ---------------- CSR gather-aggregation (fp16 feat) + fused post ----------------
__global__ void k_agg_post(float* __restrict__ bout, float* __restrict__ sout) {
    int node = (blockIdx.x * blockDim.x + threadIdx.x) >> 5;
    int lane = threadIdx.x & 31;
    if (node >= N_NODES) return;
    int e0 = g_off[node], e1 = g_off[node + 1];
    float4 a0 = make_float4(0.f, 0.f, 0.f, 0.f), a1 = a0, a2 = a0;
    int e = e0;
    for (; e + 4 <= e1; e += 4) {
        int i0 = g_csr[e], i1 = g_csr[e + 1], i2 = g_csr[e + 2], i3 = g_csr[e + 3];
        const uint2* p0 = (const uint2*)(g_feath + (size_t)i0 * CHH);
        const uint2* p1 = (const uint2*)(g_feath + (size_t)i1 * CHH);
        const uint2* p2 = (const uint2*)(g_feath + (size_t)i2 * CHH);
        const uint2* p3 = (const uint2*)(g_feath + (size_t)i3 * CHH);
        uint2 v00 = p0[lane],      v10 = p1[lane],      v20 = p2[lane],      v30 = p3[lane];
        uint2 v01 = p0[lane + 32], v11 = p1[lane + 32], v21 = p2[lane + 32], v31 = p3[lane + 32];
        uint2 v02 = p0[lane + 64], v12 = p1[lane + 64], v22 = p2[lane + 64], v32 = p3[lane + 64];
        acc_u2(a0, v00); acc_u2(a0, v10); acc_u2(a0, v20); acc_u2(a0, v30);
        acc_u2(a1, v01); acc_u2(a1, v11); acc_u2(a1, v21); acc_u2(a1, v31);
        acc_u2(a2, v02); acc_u2(a2, v12); acc_u2(a2, v22); acc_u2(a2, v32);
    }
    for (; e < e1; e++) {
        const uint2* p = (const uint2*)(g_feath + (size_t)g_csr[e] * CHH);
        acc_u2(a0, p[lane]);
        acc_u2(a1, p[lane + 32]);
        acc_u2(a2, p[lane + 64]);
    }
    ((float4*)(g_acce + (size_t)node * D))[lane] = a0;

    float ii = g_inv_in[node];
    float4 v = f4scale(a1, ii);
    float nb = sqrtf(warp_sum(v.x * v.x + v.y * v.y + v.z * v.z + v.w * v.w));
    float fb = tanhf(nb) / fmaxf(nb, 1e-7f);
    ((float4*)(bout + (size_t)node * D))[lane] = f4scale(v, fb);
    float4 u = f4scale(a2, ii);
    float ns = sqrtf(warp_sum(u.x * u.x + u.y * u.y + u.z * u.z + u.w * u.w));
    float fs = 1.0f / fmaxf(ns, 1e-12f);
    ((float4*)(sout + (size_t)node * D))[lane] = f4scale(u, fs);
}

// ---------------- launch ----------------------------------------------------------
extern "C" void kernel_launch(void* const* d_in, const int* in_sizes, int n_in,
                              void* d_out, int out_size) {
    const float* e0  = (const float*)d_in[0];
    const float* b0  = (const float*)d_in[1];
    const float* s0  = (const float*)d_in[2];
    const float* eW  = (const float*)d_in[3];
    const float* eB  = (const float*)d_in[4];
    const float* bW  = (const float*)d_in[5];
    const float* bB  = (const float*)d_in[6];
    const float* sW  = (const float*)d_in[7];
    const float* sB  = (const float*)d_in[8];
    const int*   src = (const int*)d_in[9];
    const int*   dst = (const int*)d_in[10];
    float* out = (float*)d_out;

    const int SMEM_GEMM = 2 * 128 * SP * (int)sizeof(__half);  // 69632
    cudaFuncSetAttribute(k_gemm_bs0,   cudaFuncAttributeMaxDynamicSharedMemorySize, SMEM_GEMM);
    cudaFuncSetAttribute(k_gemm3,      cudaFuncAttributeMaxDynamicSharedMemorySize, SMEM_GEMM);
    cudaFuncSetAttribute(k_gemm_elast, cudaFuncAttributeMaxDynamicSharedMemorySize, SMEM_GEMM);

    void* tmp;
    cudaGetSymbolAddress(&tmp, g_b); float* pb = (float*)tmp;
    cudaGetSymbolAddress(&tmp, g_s); float* ps = (float*)tmp;

    const int node_grid = (N_NODES + 255) / 256;
    const int edge_grid = (N_EDGES + 255) / 256;
    const int warp_grid = (N_NODES + 7) / 8;
    const int gemm_grid = (N_NODES + 127) / 128;      // 391

    // preprocessing (4 launches)
    k_zero<<<node_grid, 256>>>();
    k_deg<<<edge_grid, 256>>>(src, dst);
    k_scan_all<<<SCAN_BLOCKS, 1024>>>();
    k_scatter<<<edge_grid, 256>>>(src, dst);

    // layer 0: b/s GEMMs + e feat copy in one launch
    {
        dim3 g(gemm_grid, 3);
        k_gemm_bs0<<<g, 256, SMEM_GEMM>>>(e0, b0, s0, bW, bB, sW, sB);
    }
    // layer 0 aggregation (+ b/s post)
    k_agg_post<<<warp_grid, 256>>>(pb, ps);
    // e-GEMM(l0)->feat ch0 ; b/s-GEMM(l1)->feat ch1/2
    {
        dim3 g(gemm_grid, 3);
        k_gemm3<<<g, 256, SMEM_GEMM>>>(eW, eB,
                                       bW + (size_t)D * D, bB + D,
                                       sW + (size_t)D * D, sB + D);
    }
    // layer 1 aggregation (+ final b/s outputs)
    k_agg_post<<<warp_grid, 256>>>(out + (size_t)N_NODES * D,
                                   out + (size_t)2 * N_NODES * D);
    // final e-GEMM -> out
    k_gemm_elast<<<gemm_grid, 256, SMEM_GEMM>>>(eW + (size_t)D * D, eB + D, out);
}